// round 13
// baseline (speedup 1.0000x reference)
#include <cuda_runtime.h>
#include <math.h>

#define B_SZ 16
#define L_SZ 160000
#define T_FR 999
#define WINS 320
#define HOPS 160
#define NCO  100
#define TM   32
#define NTHREADS 256

#define PI_D 3.14159265358979323846

typedef unsigned long long ull;

// ---------------- quad-interleaved precomputed matrices ----------------
// g_Dwq[(kq*100+c)*4+q] = win[4kq+q] * D[4kq+q][c]      (kq<80)
// g_Eq [(kq*320+w)*4+q] = D[w][4kq+q]                   (kq<25)
// g_Wqi[(kq*100+j)*4+q] = W[j][4kq+q]                   (kq<25)
__device__ __align__(16) float g_Dwq[80 * 100 * 4];
__device__ __align__(16) float g_Eq [25 * 320 * 4];
__device__ __align__(16) float g_Wq1[25 * 100 * 4];
__device__ __align__(16) float g_Wq2[25 * 100 * 4];
__device__ __align__(16) float g_Wq3[25 * 100 * 4];

// ---------------- f32x2 helpers ----------------
__device__ __forceinline__ void fma2(ull& d, ull a, ull b) {
    asm("fma.rn.f32x2 %0, %1, %2, %0;" : "+l"(d) : "l"(a), "l"(b));
}
__device__ __forceinline__ float lanesum(ull v) {
    float lo, hi;
    asm("mov.b64 {%0, %1}, %2;" : "=f"(lo), "=f"(hi) : "l"(v));
    return lo + hi;
}
__device__ __forceinline__ float clip1(float x) {
    return fminf(fmaxf(x, -1.0f), 1.0f);
}

// ---------------- init kernel: build quad-interleaved matrices ----------------
__global__ void init_mats(const float* __restrict__ W1,
                          const float* __restrict__ W2,
                          const float* __restrict__ W3) {
    int idx = blockIdx.x * blockDim.x + threadIdx.x;
    if (idx < 80 * 100 * 4) {   // Dwq
        int q  = idx & 3;
        int c  = (idx >> 2) % 100;
        int kq = idx / 400;
        int k  = 4 * kq + q;    // sample index 0..319
        double d = sqrt(2.0 / (double)WINS) * cos((k + 0.5) * PI_D / (double)WINS * (double)c);
        if (c == 0) d *= sqrt(0.5);
        double win = 0.5 * (1.0 - cos(2.0 * PI_D * (double)k / (double)WINS));
        g_Dwq[idx] = (float)(win * d);
    }
    if (idx < 25 * 320 * 4) {   // Eq
        int q  = idx & 3;
        int w  = (idx >> 2) % 320;
        int kq = idx / 1280;
        int c  = 4 * kq + q;    // coefficient index 0..99
        double d = sqrt(2.0 / (double)WINS) * cos((w + 0.5) * PI_D / (double)WINS * (double)c);
        if (c == 0) d *= sqrt(0.5);
        g_Eq[idx] = (float)d;
    }
    if (idx < 25 * 100 * 4) {   // Wq1/2/3
        int q  = idx & 3;
        int j  = (idx >> 2) % 100;
        int kq = idx / 400;
        int k  = 4 * kq + q;    // input-feature index 0..99
        g_Wq1[idx] = W1[j * NCO + k];
        g_Wq2[idx] = W2[j * NCO + k];
        g_Wq3[idx] = W3[j * NCO + k];
    }
}

// smem: sig[5280] | bufA[3328] | bufB[3328]  = 47,744 B  -> 4 CTAs/SM
#define SIG_LEN  ((TM - 1) * HOPS + WINS)   // 5280
#define RM_STR   104                         // row stride (16B-aligned rows)
#define BUF_SZ   (TM * RM_STR)               // 3328
#define SMEM_FLOATS (SIG_LEN + 2 * BUF_SZ)
#define SMEM_BYTES  (SMEM_FLOATS * 4)

// ---- stage-1 DCT: K=320 (80 k-quads), weights direct from L2, 4 rows/warp ----
// DST_SMEM: write bufA row-major; else write global only.
template <bool DST_SMEM>
__device__ __forceinline__ void dct_pass(
    const float* __restrict__ sig, float* __restrict__ bufA,
    float* __restrict__ gdst, int b, int t0, int tx, int ty)
{
    const bool pred4 = (tx < 4);
    ull acc[4][4] = {};
    const ulonglong2* __restrict__ Wq = reinterpret_cast<const ulonglong2*>(g_Dwq);
    #pragma unroll 2
    for (int kq = 0; kq < 80; kq++) {
        const ulonglong2* wr = Wq + kq * 100;
        ulonglong2 w0 = wr[tx];
        ulonglong2 w1 = wr[32 + tx];
        ulonglong2 w2 = wr[64 + tx];
        ulonglong2 w3 = pred4 ? wr[96 + tx] : make_ulonglong2(0ull, 0ull);
        const int ko = kq * 4;
        #pragma unroll
        for (int i = 0; i < 4; i++) {
            ulonglong2 a = *reinterpret_cast<const ulonglong2*>(&sig[(ty + 8 * i) * HOPS + ko]);
            fma2(acc[i][0], a.x, w0.x); fma2(acc[i][0], a.y, w0.y);
            fma2(acc[i][1], a.x, w1.x); fma2(acc[i][1], a.y, w1.y);
            fma2(acc[i][2], a.x, w2.x); fma2(acc[i][2], a.y, w2.y);
            fma2(acc[i][3], a.x, w3.x); fma2(acc[i][3], a.y, w3.y);
        }
    }
    #pragma unroll
    for (int i = 0; i < 4; i++) {
        const int r = ty + 8 * i;
        const int t = t0 + r;
        #pragma unroll
        for (int jb = 0; jb < 4; jb++) {
            const int j = tx + 32 * jb;
            const bool jv = (jb < 3) || pred4;
            float val = clip1(lanesum(acc[i][jb]));
            if (DST_SMEM) {
                if (jv) bufA[r * RM_STR + j] = val;
            } else if (jv && t < T_FR) {
                gdst[((size_t)b * T_FR + t) * NCO + j] = val;
            }
        }
    }
}

// ---- MLP stage: K=100 (25 k-quads), direct LDG. ACT: 0 prelu, 1 tanh. ----
template <int ACT, bool WRITE_G>
__device__ __forceinline__ void mlp_stage(
    const float* __restrict__ Asm, float* __restrict__ Bsm,
    const float* __restrict__ Wqg, const float* __restrict__ bias, float alpha,
    int tx, int ty, float* __restrict__ gout, int b, int t0)
{
    const bool pred4 = (tx < 4);
    ull acc[4][4] = {};
    const ulonglong2* __restrict__ Wq = reinterpret_cast<const ulonglong2*>(Wqg);
    #pragma unroll 2
    for (int kq = 0; kq < 25; kq++) {
        const ulonglong2* wr = Wq + kq * 100;
        ulonglong2 w0 = wr[tx];
        ulonglong2 w1 = wr[32 + tx];
        ulonglong2 w2 = wr[64 + tx];
        ulonglong2 w3 = pred4 ? wr[96 + tx] : make_ulonglong2(0ull, 0ull);
        const int ko = kq * 4;
        #pragma unroll
        for (int i = 0; i < 4; i++) {
            ulonglong2 a = *reinterpret_cast<const ulonglong2*>(&Asm[(ty + 8 * i) * RM_STR + ko]);
            fma2(acc[i][0], a.x, w0.x); fma2(acc[i][0], a.y, w0.y);
            fma2(acc[i][1], a.x, w1.x); fma2(acc[i][1], a.y, w1.y);
            fma2(acc[i][2], a.x, w2.x); fma2(acc[i][2], a.y, w2.y);
            fma2(acc[i][3], a.x, w3.x); fma2(acc[i][3], a.y, w3.y);
        }
    }
    float bj[4];
    bj[0] = bias[tx];
    bj[1] = bias[32 + tx];
    bj[2] = bias[64 + tx];
    bj[3] = pred4 ? bias[96 + tx] : 0.f;
    #pragma unroll
    for (int i = 0; i < 4; i++) {
        const int r = ty + 8 * i;
        const int t = t0 + r;
        #pragma unroll
        for (int jb = 0; jb < 4; jb++) {
            const int j = tx + 32 * jb;
            const bool jv = (jb < 3) || pred4;
            float val = lanesum(acc[i][jb]) + bj[jb];
            if (ACT == 0) val = (val >= 0.f) ? val : alpha * val;
            else          val = tanhf(val);
            if (jv) Bsm[r * RM_STR + j] = val;
            if (WRITE_G && jv && t < T_FR)
                gout[((size_t)b * T_FR + t) * NCO + j] = val;
        }
    }
}

__device__ __forceinline__ void load_seg(const float* __restrict__ g, float* __restrict__ s,
                                         int seglen, int tid) {
    const float4* g4 = reinterpret_cast<const float4*>(g);
    float4* s4 = reinterpret_cast<float4*>(s);
    const int segv = seglen >> 2;
    const float4 z4 = make_float4(0.f, 0.f, 0.f, 0.f);
    for (int i = tid; i < (SIG_LEN >> 2); i += NTHREADS)
        s4[i] = (i < segv) ? g4[i] : z4;
}

__global__ __launch_bounds__(NTHREADS, 4) void fused_kernel(
    const float* __restrict__ noisy, const float* __restrict__ clean,
    const float* __restrict__ b1, const float* __restrict__ p1g,
    const float* __restrict__ b2, const float* __restrict__ p2g,
    const float* __restrict__ b3,
    float* __restrict__ out_dct, float* __restrict__ cln_dct,
    float* __restrict__ out_sp)
{
    extern __shared__ float smem[];
    float* sig  = smem;
    float* bufA = smem + SIG_LEN;
    float* bufB = bufA + BUF_SZ;

    const int tid = threadIdx.x;
    const int tx  = tid & 31;
    const int ty  = tid >> 5;          // warp 0..7; rows ty+8i, i=0..3
    const int b   = blockIdx.y;
    const int t0  = blockIdx.x * TM;
    const int nf  = min(TM, T_FR - t0);
    const int seglen = (nf - 1) * HOPS + WINS;

    const float alpha1 = p1g[0];
    const float alpha2 = p2g[0];

    // ---- clean: DCT -> global ----
    load_seg(clean + (size_t)b * L_SZ + (size_t)t0 * HOPS, sig, seglen, tid);
    __syncthreads();
    dct_pass<false>(sig, bufA, cln_dct, b, t0, tx, ty);
    __syncthreads();

    // ---- noisy: DCT -> bufA ----
    load_seg(noisy + (size_t)b * L_SZ + (size_t)t0 * HOPS, sig, seglen, tid);
    __syncthreads();
    dct_pass<true>(sig, bufA, nullptr, b, t0, tx, ty);
    __syncthreads();

    // ---- MLP ----
    mlp_stage<0, false>(bufA, bufB, g_Wq1, b1, alpha1, tx, ty, nullptr, b, t0);
    __syncthreads();
    mlp_stage<0, false>(bufB, bufA, g_Wq2, b2, alpha2, tx, ty, nullptr, b, t0);
    __syncthreads();
    mlp_stage<1, true >(bufA, bufB, g_Wq3, b3, 0.f,    tx, ty, out_dct, b, t0);
    __syncthreads();

    // ---- IDCT: K=100 (25 k-quads), 5 passes x 2 col-blocks (low reg pressure) ----
    const ulonglong2* __restrict__ Eq = reinterpret_cast<const ulonglong2*>(g_Eq);
    #pragma unroll 1
    for (int h = 0; h < 5; h++) {
        ull acc[4][2] = {};
        #pragma unroll 1
        for (int kq = 0; kq < 25; kq++) {
            const ulonglong2* er = Eq + kq * 320;
            ulonglong2 w0 = er[tx + 32 * (2 * h)];
            ulonglong2 w1 = er[tx + 32 * (2 * h + 1)];
            const int ko = kq * 4;
            #pragma unroll
            for (int i = 0; i < 4; i++) {
                ulonglong2 a = *reinterpret_cast<const ulonglong2*>(&bufB[(ty + 8 * i) * RM_STR + ko]);
                fma2(acc[i][0], a.x, w0.x); fma2(acc[i][0], a.y, w0.y);
                fma2(acc[i][1], a.x, w1.x); fma2(acc[i][1], a.y, w1.y);
            }
        }
        #pragma unroll
        for (int i = 0; i < 4; i++) {
            const int t = t0 + ty + 8 * i;
            if (t < T_FR) {
                float* dst = out_sp + (size_t)b * L_SZ + (size_t)t * HOPS;
                atomicAdd(&dst[tx + 32 * (2 * h)],     lanesum(acc[i][0]));
                atomicAdd(&dst[tx + 32 * (2 * h + 1)], lanesum(acc[i][1]));
            }
        }
    }
}

// ---------------- launch ----------------
extern "C" void kernel_launch(void* const* d_in, const int* in_sizes, int n_in,
                              void* d_out, int out_size) {
    const float* noisy = (const float*)d_in[0];
    const float* clean = (const float*)d_in[1];
    const float* W1    = (const float*)d_in[2];
    const float* b1    = (const float*)d_in[3];
    const float* p1    = (const float*)d_in[4];
    const float* W2    = (const float*)d_in[5];
    const float* b2    = (const float*)d_in[6];
    const float* p2    = (const float*)d_in[7];
    const float* W3    = (const float*)d_in[8];
    const float* b3    = (const float*)d_in[9];

    float* out      = (float*)d_out;
    float* out_dct  = out;                                   // [16, 999, 100]
    float* cln_dct  = out + (size_t)B_SZ * T_FR * NCO;       // [16, 999, 100]
    float* out_sp   = out + 2 * (size_t)B_SZ * T_FR * NCO;   // [16, 160000]

    cudaMemsetAsync(out_sp, 0, (size_t)B_SZ * L_SZ * sizeof(float), 0);

    init_mats<<<(80 * 100 * 4 + 255) / 256, 256>>>(W1, W2, W3);

    cudaFuncSetAttribute(fused_kernel, cudaFuncAttributeMaxDynamicSharedMemorySize, SMEM_BYTES);
    dim3 grid((T_FR + TM - 1) / TM, B_SZ);
    fused_kernel<<<grid, NTHREADS, SMEM_BYTES>>>(noisy, clean, b1, p1, b2, p2, b3,
                                                 out_dct, cln_dct, out_sp);
}

// round 14
// speedup vs baseline: 1.1233x; 1.1233x over previous
#include <cuda_runtime.h>
#include <math.h>

#define B_SZ 16
#define L_SZ 160000
#define T_FR 999
#define WINS 320
#define HOPS 160
#define NCO  100
#define TM   40
#define NTHREADS 256

#define PI_D 3.14159265358979323846

typedef unsigned long long ull;

// ---------------- quad-interleaved precomputed matrices ----------------
// g_Dwq[(kq*100+c)*4+q] = win[4kq+q] * D[4kq+q][c]      (kq<80)
// g_Eq [(kq*320+w)*4+q] = D[w][4kq+q]                   (kq<25)
// g_Wqi[(kq*100+j)*4+q] = W[j][4kq+q]                   (kq<25)
__device__ __align__(16) float g_Dwq[80 * 100 * 4];
__device__ __align__(16) float g_Eq [25 * 320 * 4];
__device__ __align__(16) float g_Wq1[25 * 100 * 4];
__device__ __align__(16) float g_Wq2[25 * 100 * 4];
__device__ __align__(16) float g_Wq3[25 * 100 * 4];

// ---------------- f32x2 helpers ----------------
__device__ __forceinline__ void fma2(ull& d, ull a, ull b) {
    asm("fma.rn.f32x2 %0, %1, %2, %0;" : "+l"(d) : "l"(a), "l"(b));
}
__device__ __forceinline__ float lanesum(ull v) {
    float lo, hi;
    asm("mov.b64 {%0, %1}, %2;" : "=f"(lo), "=f"(hi) : "l"(v));
    return lo + hi;
}
__device__ __forceinline__ float clip1(float x) {
    return fminf(fmaxf(x, -1.0f), 1.0f);
}

// ---------------- init kernel: build quad-interleaved matrices ----------------
__global__ void init_mats(const float* __restrict__ W1,
                          const float* __restrict__ W2,
                          const float* __restrict__ W3) {
    int idx = blockIdx.x * blockDim.x + threadIdx.x;
    if (idx < 80 * 100 * 4) {   // Dwq
        int q  = idx & 3;
        int c  = (idx >> 2) % 100;
        int kq = idx / 400;
        int k  = 4 * kq + q;    // sample index 0..319
        double d = sqrt(2.0 / (double)WINS) * cos((k + 0.5) * PI_D / (double)WINS * (double)c);
        if (c == 0) d *= sqrt(0.5);
        double win = 0.5 * (1.0 - cos(2.0 * PI_D * (double)k / (double)WINS));
        g_Dwq[idx] = (float)(win * d);
    }
    if (idx < 25 * 320 * 4) {   // Eq
        int q  = idx & 3;
        int w  = (idx >> 2) % 320;
        int kq = idx / 1280;
        int c  = 4 * kq + q;    // coefficient index 0..99
        double d = sqrt(2.0 / (double)WINS) * cos((w + 0.5) * PI_D / (double)WINS * (double)c);
        if (c == 0) d *= sqrt(0.5);
        g_Eq[idx] = (float)d;
    }
    if (idx < 25 * 100 * 4) {   // Wq1/2/3
        int q  = idx & 3;
        int j  = (idx >> 2) % 100;
        int kq = idx / 400;
        int k  = 4 * kq + q;    // input-feature index 0..99
        g_Wq1[idx] = W1[j * NCO + k];
        g_Wq2[idx] = W2[j * NCO + k];
        g_Wq3[idx] = W3[j * NCO + k];
    }
}

// smem: sig[6560] | bufA[4160] | bufB[4160]  = 59,520 B  -> 3 CTAs/SM
#define SIG_LEN  ((TM - 1) * HOPS + WINS)   // 6560
#define RM_STR   104                         // row stride (16B-aligned rows)
#define BUF_SZ   (TM * RM_STR)               // 4160
#define SMEM_FLOATS (SIG_LEN + 2 * BUF_SZ)
#define SMEM_BYTES  (SMEM_FLOATS * 4)

// ---- stage-1 DCT: K=320 (80 k-quads), weights direct from L2/L1, 5 rows/warp ----
// DST_SMEM: write bufA row-major; else write global only.
template <bool DST_SMEM>
__device__ __forceinline__ void dct_pass(
    const float* __restrict__ sig, float* __restrict__ bufA,
    float* __restrict__ gdst, int b, int t0, int tx, int ty)
{
    const bool pred4 = (tx < 4);
    ull acc[5][4] = {};
    const ulonglong2* __restrict__ Wq = reinterpret_cast<const ulonglong2*>(g_Dwq);
    #pragma unroll 2
    for (int kq = 0; kq < 80; kq++) {
        const ulonglong2* wr = Wq + kq * 100;
        ulonglong2 w0 = wr[tx];
        ulonglong2 w1 = wr[32 + tx];
        ulonglong2 w2 = wr[64 + tx];
        ulonglong2 w3 = pred4 ? wr[96 + tx] : make_ulonglong2(0ull, 0ull);
        const int ko = kq * 4;
        #pragma unroll
        for (int i = 0; i < 5; i++) {
            ulonglong2 a = *reinterpret_cast<const ulonglong2*>(&sig[(ty + 8 * i) * HOPS + ko]);
            fma2(acc[i][0], a.x, w0.x); fma2(acc[i][0], a.y, w0.y);
            fma2(acc[i][1], a.x, w1.x); fma2(acc[i][1], a.y, w1.y);
            fma2(acc[i][2], a.x, w2.x); fma2(acc[i][2], a.y, w2.y);
            fma2(acc[i][3], a.x, w3.x); fma2(acc[i][3], a.y, w3.y);
        }
    }
    #pragma unroll
    for (int i = 0; i < 5; i++) {
        const int r = ty + 8 * i;
        const int t = t0 + r;
        #pragma unroll
        for (int jb = 0; jb < 4; jb++) {
            const int j = tx + 32 * jb;
            const bool jv = (jb < 3) || pred4;
            float val = clip1(lanesum(acc[i][jb]));
            if (DST_SMEM) {
                if (jv) bufA[r * RM_STR + j] = val;
            } else if (jv && t < T_FR) {
                gdst[((size_t)b * T_FR + t) * NCO + j] = val;
            }
        }
    }
}

// ---- MLP stage: K=100 (25 k-quads), direct LDG. ACT: 0 prelu, 1 tanh. ----
template <int ACT, bool WRITE_G>
__device__ __forceinline__ void mlp_stage(
    const float* __restrict__ Asm, float* __restrict__ Bsm,
    const float* __restrict__ Wqg, const float* __restrict__ bias, float alpha,
    int tx, int ty, float* __restrict__ gout, int b, int t0)
{
    const bool pred4 = (tx < 4);
    ull acc[5][4] = {};
    const ulonglong2* __restrict__ Wq = reinterpret_cast<const ulonglong2*>(Wqg);
    #pragma unroll 2
    for (int kq = 0; kq < 25; kq++) {
        const ulonglong2* wr = Wq + kq * 100;
        ulonglong2 w0 = wr[tx];
        ulonglong2 w1 = wr[32 + tx];
        ulonglong2 w2 = wr[64 + tx];
        ulonglong2 w3 = pred4 ? wr[96 + tx] : make_ulonglong2(0ull, 0ull);
        const int ko = kq * 4;
        #pragma unroll
        for (int i = 0; i < 5; i++) {
            ulonglong2 a = *reinterpret_cast<const ulonglong2*>(&Asm[(ty + 8 * i) * RM_STR + ko]);
            fma2(acc[i][0], a.x, w0.x); fma2(acc[i][0], a.y, w0.y);
            fma2(acc[i][1], a.x, w1.x); fma2(acc[i][1], a.y, w1.y);
            fma2(acc[i][2], a.x, w2.x); fma2(acc[i][2], a.y, w2.y);
            fma2(acc[i][3], a.x, w3.x); fma2(acc[i][3], a.y, w3.y);
        }
    }
    float bj[4];
    bj[0] = bias[tx];
    bj[1] = bias[32 + tx];
    bj[2] = bias[64 + tx];
    bj[3] = pred4 ? bias[96 + tx] : 0.f;
    #pragma unroll
    for (int i = 0; i < 5; i++) {
        const int r = ty + 8 * i;
        const int t = t0 + r;
        #pragma unroll
        for (int jb = 0; jb < 4; jb++) {
            const int j = tx + 32 * jb;
            const bool jv = (jb < 3) || pred4;
            float val = lanesum(acc[i][jb]) + bj[jb];
            if (ACT == 0) val = (val >= 0.f) ? val : alpha * val;
            else          val = tanhf(val);
            if (jv) Bsm[r * RM_STR + j] = val;
            if (WRITE_G && jv && t < T_FR)
                gout[((size_t)b * T_FR + t) * NCO + j] = val;
        }
    }
}

__device__ __forceinline__ void load_seg(const float* __restrict__ g, float* __restrict__ s,
                                         int seglen, int tid) {
    const float4* g4 = reinterpret_cast<const float4*>(g);
    float4* s4 = reinterpret_cast<float4*>(s);
    const int segv = seglen >> 2;
    const float4 z4 = make_float4(0.f, 0.f, 0.f, 0.f);
    for (int i = tid; i < (SIG_LEN >> 2); i += NTHREADS)
        s4[i] = (i < segv) ? g4[i] : z4;
}

__global__ __launch_bounds__(NTHREADS, 3) void fused_kernel(
    const float* __restrict__ noisy, const float* __restrict__ clean,
    const float* __restrict__ b1, const float* __restrict__ p1g,
    const float* __restrict__ b2, const float* __restrict__ p2g,
    const float* __restrict__ b3,
    float* __restrict__ out_dct, float* __restrict__ cln_dct,
    float* __restrict__ out_sp)
{
    extern __shared__ float smem[];
    float* sig  = smem;
    float* bufA = smem + SIG_LEN;
    float* bufB = bufA + BUF_SZ;

    const int tid = threadIdx.x;
    const int tx  = tid & 31;
    const int ty  = tid >> 5;          // warp 0..7; rows ty+8i, i=0..4
    const int b   = blockIdx.y;
    const int t0  = blockIdx.x * TM;
    const int nf  = min(TM, T_FR - t0);
    const int seglen = (nf - 1) * HOPS + WINS;

    const float alpha1 = p1g[0];
    const float alpha2 = p2g[0];

    // ---- clean: DCT -> global ----
    load_seg(clean + (size_t)b * L_SZ + (size_t)t0 * HOPS, sig, seglen, tid);
    __syncthreads();
    dct_pass<false>(sig, bufA, cln_dct, b, t0, tx, ty);
    __syncthreads();

    // ---- noisy: DCT -> bufA ----
    load_seg(noisy + (size_t)b * L_SZ + (size_t)t0 * HOPS, sig, seglen, tid);
    __syncthreads();
    dct_pass<true>(sig, bufA, nullptr, b, t0, tx, ty);
    __syncthreads();

    // ---- MLP ----
    mlp_stage<0, false>(bufA, bufB, g_Wq1, b1, alpha1, tx, ty, nullptr, b, t0);
    __syncthreads();
    mlp_stage<0, false>(bufB, bufA, g_Wq2, b2, alpha2, tx, ty, nullptr, b, t0);
    __syncthreads();
    mlp_stage<1, true >(bufA, bufB, g_Wq3, b3, 0.f,    tx, ty, out_dct, b, t0);
    __syncthreads();

    // ---- IDCT: K=100 (25 k-quads), 5 passes x 2 col-blocks (low reg pressure) ----
    const ulonglong2* __restrict__ Eq = reinterpret_cast<const ulonglong2*>(g_Eq);
    #pragma unroll 1
    for (int h = 0; h < 5; h++) {
        ull acc[5][2] = {};
        #pragma unroll 1
        for (int kq = 0; kq < 25; kq++) {
            const ulonglong2* er = Eq + kq * 320;
            ulonglong2 w0 = er[tx + 32 * (2 * h)];
            ulonglong2 w1 = er[tx + 32 * (2 * h + 1)];
            const int ko = kq * 4;
            #pragma unroll
            for (int i = 0; i < 5; i++) {
                ulonglong2 a = *reinterpret_cast<const ulonglong2*>(&bufB[(ty + 8 * i) * RM_STR + ko]);
                fma2(acc[i][0], a.x, w0.x); fma2(acc[i][0], a.y, w0.y);
                fma2(acc[i][1], a.x, w1.x); fma2(acc[i][1], a.y, w1.y);
            }
        }
        #pragma unroll
        for (int i = 0; i < 5; i++) {
            const int t = t0 + ty + 8 * i;
            if (t < T_FR) {
                float* dst = out_sp + (size_t)b * L_SZ + (size_t)t * HOPS;
                atomicAdd(&dst[tx + 32 * (2 * h)],     lanesum(acc[i][0]));
                atomicAdd(&dst[tx + 32 * (2 * h + 1)], lanesum(acc[i][1]));
            }
        }
    }
}

// ---------------- launch ----------------
extern "C" void kernel_launch(void* const* d_in, const int* in_sizes, int n_in,
                              void* d_out, int out_size) {
    const float* noisy = (const float*)d_in[0];
    const float* clean = (const float*)d_in[1];
    const float* W1    = (const float*)d_in[2];
    const float* b1    = (const float*)d_in[3];
    const float* p1    = (const float*)d_in[4];
    const float* W2    = (const float*)d_in[5];
    const float* b2    = (const float*)d_in[6];
    const float* p2    = (const float*)d_in[7];
    const float* W3    = (const float*)d_in[8];
    const float* b3    = (const float*)d_in[9];

    float* out      = (float*)d_out;
    float* out_dct  = out;                                   // [16, 999, 100]
    float* cln_dct  = out + (size_t)B_SZ * T_FR * NCO;       // [16, 999, 100]
    float* out_sp   = out + 2 * (size_t)B_SZ * T_FR * NCO;   // [16, 160000]

    cudaMemsetAsync(out_sp, 0, (size_t)B_SZ * L_SZ * sizeof(float), 0);

    init_mats<<<(80 * 100 * 4 + 255) / 256, 256>>>(W1, W2, W3);

    cudaFuncSetAttribute(fused_kernel, cudaFuncAttributeMaxDynamicSharedMemorySize, SMEM_BYTES);
    dim3 grid((T_FR + TM - 1) / TM, B_SZ);
    fused_kernel<<<grid, NTHREADS, SMEM_BYTES>>>(noisy, clean, b1, p1, b2, p2, b3,
                                                 out_dct, cln_dct, out_sp);
}

// round 16
// speedup vs baseline: 1.4322x; 1.2750x over previous
#include <cuda_runtime.h>
#include <math.h>

#define B_SZ 16
#define L_SZ 160000
#define T_FR 999
#define WINS 320
#define HOPS 160
#define NCO  100
#define TM   56
#define NTHREADS 256

#define PI_D 3.14159265358979323846

typedef unsigned long long ull;

// ---------------- quad-interleaved precomputed matrices ----------------
// g_Dwq[(kq*100+c)*4+q] = win[4kq+q] * D[4kq+q][c]      (kq<80)
// g_Eq [(kq*320+w)*4+q] = D[w][4kq+q]                   (kq<25)
// g_Wqi[(kq*100+j)*4+q] = W[j][4kq+q]                   (kq<25)
__device__ __align__(16) float g_Dwq[80 * 100 * 4];
__device__ __align__(16) float g_Eq [25 * 320 * 4];
__device__ __align__(16) float g_Wq1[25 * 100 * 4];
__device__ __align__(16) float g_Wq2[25 * 100 * 4];
__device__ __align__(16) float g_Wq3[25 * 100 * 4];

// ---------------- f32x2 helpers ----------------
__device__ __forceinline__ void fma2(ull& d, ull a, ull b) {
    asm("fma.rn.f32x2 %0, %1, %2, %0;" : "+l"(d) : "l"(a), "l"(b));
}
__device__ __forceinline__ float lanesum(ull v) {
    float lo, hi;
    asm("mov.b64 {%0, %1}, %2;" : "=f"(lo), "=f"(hi) : "l"(v));
    return lo + hi;
}
__device__ __forceinline__ float clip1(float x) {
    return fminf(fmaxf(x, -1.0f), 1.0f);
}

// ---------------- init kernel: build quad-interleaved matrices ----------------
__global__ void init_mats(const float* __restrict__ W1,
                          const float* __restrict__ W2,
                          const float* __restrict__ W3) {
    int idx = blockIdx.x * blockDim.x + threadIdx.x;
    if (idx < 80 * 100 * 4) {   // Dwq
        int q  = idx & 3;
        int c  = (idx >> 2) % 100;
        int kq = idx / 400;
        int k  = 4 * kq + q;    // sample index 0..319
        double d = sqrt(2.0 / (double)WINS) * cos((k + 0.5) * PI_D / (double)WINS * (double)c);
        if (c == 0) d *= sqrt(0.5);
        double win = 0.5 * (1.0 - cos(2.0 * PI_D * (double)k / (double)WINS));
        g_Dwq[idx] = (float)(win * d);
    }
    if (idx < 25 * 320 * 4) {   // Eq
        int q  = idx & 3;
        int w  = (idx >> 2) % 320;
        int kq = idx / 1280;
        int c  = 4 * kq + q;    // coefficient index 0..99
        double d = sqrt(2.0 / (double)WINS) * cos((w + 0.5) * PI_D / (double)WINS * (double)c);
        if (c == 0) d *= sqrt(0.5);
        g_Eq[idx] = (float)d;
    }
    if (idx < 25 * 100 * 4) {   // Wq1/2/3
        int q  = idx & 3;
        int j  = (idx >> 2) % 100;
        int kq = idx / 400;
        int k  = 4 * kq + q;    // input-feature index 0..99
        g_Wq1[idx] = W1[j * NCO + k];
        g_Wq2[idx] = W2[j * NCO + k];
        g_Wq3[idx] = W3[j * NCO + k];
    }
}

// smem: sig[9120] | bufA[5824] | bufB[5824]  = 83,072 B  -> 2 CTAs/SM
#define SIG_LEN  ((TM - 1) * HOPS + WINS)   // 9120
#define RM_STR   104                         // row stride (16B-aligned rows)
#define BUF_SZ   (TM * RM_STR)               // 5824
#define SMEM_FLOATS (SIG_LEN + 2 * BUF_SZ)
#define SMEM_BYTES  (SMEM_FLOATS * 4)

// ---- stage-1 DCT: K=320 (80 k-quads), 7 rows/warp, cols = 3x32 main + 4 tail ----
// DST_SMEM: write bufA row-major; else write global only.
template <bool DST_SMEM>
__device__ __forceinline__ void dct_pass(
    const float* __restrict__ sig, float* __restrict__ bufA,
    float* __restrict__ gdst, int b, int t0, int tx, int ty)
{
    const bool tact = (tx < 28);
    const int  rl = tact ? (tx >> 2) : 0;   // FIX: clamp inactive lanes to a valid row
    const int  cl = tx & 3;                 // tail: col offset 0..3
    ull acc[7][3] = {};
    ull acct = 0;
    const ulonglong2* __restrict__ Wq = reinterpret_cast<const ulonglong2*>(g_Dwq);
    #pragma unroll 2
    for (int kq = 0; kq < 80; kq++) {
        const ulonglong2* wr = Wq + kq * 100;
        ulonglong2 w0 = wr[tx];
        ulonglong2 w1 = wr[32 + tx];
        ulonglong2 w2 = wr[64 + tx];
        ulonglong2 wt = tact ? wr[96 + cl] : make_ulonglong2(0ull, 0ull);
        const int ko = kq * 4;
        #pragma unroll
        for (int i = 0; i < 7; i++) {
            ulonglong2 a = *reinterpret_cast<const ulonglong2*>(&sig[(ty + 8 * i) * HOPS + ko]);
            fma2(acc[i][0], a.x, w0.x); fma2(acc[i][0], a.y, w0.y);
            fma2(acc[i][1], a.x, w1.x); fma2(acc[i][1], a.y, w1.y);
            fma2(acc[i][2], a.x, w2.x); fma2(acc[i][2], a.y, w2.y);
        }
        ulonglong2 at = *reinterpret_cast<const ulonglong2*>(&sig[(ty + 8 * rl) * HOPS + ko]);
        fma2(acct, at.x, wt.x); fma2(acct, at.y, wt.y);
    }
    #pragma unroll
    for (int i = 0; i < 7; i++) {
        const int r = ty + 8 * i;
        const int t = t0 + r;
        #pragma unroll
        for (int jb = 0; jb < 3; jb++) {
            const int j = tx + 32 * jb;
            float val = clip1(lanesum(acc[i][jb]));
            if (DST_SMEM) bufA[r * RM_STR + j] = val;
            else if (t < T_FR) gdst[((size_t)b * T_FR + t) * NCO + j] = val;
        }
    }
    if (tact) {
        const int r = ty + 8 * rl;
        const int t = t0 + r;
        float val = clip1(lanesum(acct));
        if (DST_SMEM) bufA[r * RM_STR + 96 + cl] = val;
        else if (t < T_FR) gdst[((size_t)b * T_FR + t) * NCO + 96 + cl] = val;
    }
}

// ---- MLP stage: K=100 (25 k-quads), same 96+4 col split. ACT: 0 prelu, 1 tanh. ----
template <int ACT, bool WRITE_G>
__device__ __forceinline__ void mlp_stage(
    const float* __restrict__ Asm, float* __restrict__ Bsm,
    const float* __restrict__ Wqg, const float* __restrict__ bias, float alpha,
    int tx, int ty, float* __restrict__ gout, int b, int t0)
{
    const bool tact = (tx < 28);
    const int  rl = tact ? (tx >> 2) : 0;   // FIX: clamp inactive lanes to a valid row
    const int  cl = tx & 3;
    ull acc[7][3] = {};
    ull acct = 0;
    const ulonglong2* __restrict__ Wq = reinterpret_cast<const ulonglong2*>(Wqg);
    #pragma unroll 2
    for (int kq = 0; kq < 25; kq++) {
        const ulonglong2* wr = Wq + kq * 100;
        ulonglong2 w0 = wr[tx];
        ulonglong2 w1 = wr[32 + tx];
        ulonglong2 w2 = wr[64 + tx];
        ulonglong2 wt = tact ? wr[96 + cl] : make_ulonglong2(0ull, 0ull);
        const int ko = kq * 4;
        #pragma unroll
        for (int i = 0; i < 7; i++) {
            ulonglong2 a = *reinterpret_cast<const ulonglong2*>(&Asm[(ty + 8 * i) * RM_STR + ko]);
            fma2(acc[i][0], a.x, w0.x); fma2(acc[i][0], a.y, w0.y);
            fma2(acc[i][1], a.x, w1.x); fma2(acc[i][1], a.y, w1.y);
            fma2(acc[i][2], a.x, w2.x); fma2(acc[i][2], a.y, w2.y);
        }
        ulonglong2 at = *reinterpret_cast<const ulonglong2*>(&Asm[(ty + 8 * rl) * RM_STR + ko]);
        fma2(acct, at.x, wt.x); fma2(acct, at.y, wt.y);
    }
    float bj[3];
    bj[0] = bias[tx];
    bj[1] = bias[32 + tx];
    bj[2] = bias[64 + tx];
    const float bt = tact ? bias[96 + cl] : 0.f;
    #pragma unroll
    for (int i = 0; i < 7; i++) {
        const int r = ty + 8 * i;
        const int t = t0 + r;
        #pragma unroll
        for (int jb = 0; jb < 3; jb++) {
            const int j = tx + 32 * jb;
            float val = lanesum(acc[i][jb]) + bj[jb];
            if (ACT == 0) val = (val >= 0.f) ? val : alpha * val;
            else          val = tanhf(val);
            Bsm[r * RM_STR + j] = val;
            if (WRITE_G && t < T_FR)
                gout[((size_t)b * T_FR + t) * NCO + j] = val;
        }
    }
    if (tact) {
        const int r = ty + 8 * rl;
        const int t = t0 + r;
        float val = lanesum(acct) + bt;
        if (ACT == 0) val = (val >= 0.f) ? val : alpha * val;
        else          val = tanhf(val);
        Bsm[r * RM_STR + 96 + cl] = val;
        if (WRITE_G && t < T_FR)
            gout[((size_t)b * T_FR + t) * NCO + 96 + cl] = val;
    }
}

__device__ __forceinline__ void load_seg(const float* __restrict__ g, float* __restrict__ s,
                                         int seglen, int tid) {
    const float4* g4 = reinterpret_cast<const float4*>(g);
    float4* s4 = reinterpret_cast<float4*>(s);
    const int segv = seglen >> 2;
    const float4 z4 = make_float4(0.f, 0.f, 0.f, 0.f);
    for (int i = tid; i < (SIG_LEN >> 2); i += NTHREADS)
        s4[i] = (i < segv) ? g4[i] : z4;
}

__global__ __launch_bounds__(NTHREADS, 2) void fused_kernel(
    const float* __restrict__ noisy, const float* __restrict__ clean,
    const float* __restrict__ b1, const float* __restrict__ p1g,
    const float* __restrict__ b2, const float* __restrict__ p2g,
    const float* __restrict__ b3,
    float* __restrict__ out_dct, float* __restrict__ cln_dct,
    float* __restrict__ out_sp)
{
    extern __shared__ float smem[];
    float* sig  = smem;
    float* bufA = smem + SIG_LEN;
    float* bufB = bufA + BUF_SZ;

    const int tid = threadIdx.x;
    const int tx  = tid & 31;
    const int ty  = tid >> 5;          // warp 0..7; rows ty+8i, i=0..6
    const int b   = blockIdx.y;
    const int t0  = blockIdx.x * TM;
    const int nf  = min(TM, T_FR - t0);
    const int seglen = (nf - 1) * HOPS + WINS;

    const float alpha1 = p1g[0];
    const float alpha2 = p2g[0];

    // ---- clean: DCT -> global ----
    load_seg(clean + (size_t)b * L_SZ + (size_t)t0 * HOPS, sig, seglen, tid);
    __syncthreads();
    dct_pass<false>(sig, bufA, cln_dct, b, t0, tx, ty);
    __syncthreads();

    // ---- noisy: DCT -> bufA ----
    load_seg(noisy + (size_t)b * L_SZ + (size_t)t0 * HOPS, sig, seglen, tid);
    __syncthreads();
    dct_pass<true>(sig, bufA, nullptr, b, t0, tx, ty);
    __syncthreads();

    // ---- MLP ----
    mlp_stage<0, false>(bufA, bufB, g_Wq1, b1, alpha1, tx, ty, nullptr, b, t0);
    __syncthreads();
    mlp_stage<0, false>(bufB, bufA, g_Wq2, b2, alpha2, tx, ty, nullptr, b, t0);
    __syncthreads();
    mlp_stage<1, true >(bufA, bufB, g_Wq3, b3, 0.f,    tx, ty, out_dct, b, t0);
    __syncthreads();

    // ---- IDCT: K=100 (25 k-quads), two column halves (zero col waste), + OLA ----
    const ulonglong2* __restrict__ Eq = reinterpret_cast<const ulonglong2*>(g_Eq);
    #pragma unroll 1
    for (int h = 0; h < 2; h++) {
        ull acc[7][5] = {};
        #pragma unroll 1
        for (int kq = 0; kq < 25; kq++) {
            const ulonglong2* er = Eq + kq * 320;
            ulonglong2 w[5];
            #pragma unroll
            for (int jj = 0; jj < 5; jj++) w[jj] = er[tx + 32 * (5 * h + jj)];
            const int ko = kq * 4;
            #pragma unroll
            for (int i = 0; i < 7; i++) {
                ulonglong2 a = *reinterpret_cast<const ulonglong2*>(&bufB[(ty + 8 * i) * RM_STR + ko]);
                #pragma unroll
                for (int jj = 0; jj < 5; jj++) {
                    fma2(acc[i][jj], a.x, w[jj].x);
                    fma2(acc[i][jj], a.y, w[jj].y);
                }
            }
        }
        #pragma unroll
        for (int i = 0; i < 7; i++) {
            const int t = t0 + ty + 8 * i;
            if (t < T_FR) {
                float* dst = out_sp + (size_t)b * L_SZ + (size_t)t * HOPS;
                #pragma unroll
                for (int jj = 0; jj < 5; jj++)
                    atomicAdd(&dst[tx + 32 * (5 * h + jj)], lanesum(acc[i][jj]));
            }
        }
    }
}

// ---------------- launch ----------------
extern "C" void kernel_launch(void* const* d_in, const int* in_sizes, int n_in,
                              void* d_out, int out_size) {
    const float* noisy = (const float*)d_in[0];
    const float* clean = (const float*)d_in[1];
    const float* W1    = (const float*)d_in[2];
    const float* b1    = (const float*)d_in[3];
    const float* p1    = (const float*)d_in[4];
    const float* W2    = (const float*)d_in[5];
    const float* b2    = (const float*)d_in[6];
    const float* p2    = (const float*)d_in[7];
    const float* W3    = (const float*)d_in[8];
    const float* b3    = (const float*)d_in[9];

    float* out      = (float*)d_out;
    float* out_dct  = out;                                   // [16, 999, 100]
    float* cln_dct  = out + (size_t)B_SZ * T_FR * NCO;       // [16, 999, 100]
    float* out_sp   = out + 2 * (size_t)B_SZ * T_FR * NCO;   // [16, 160000]

    cudaMemsetAsync(out_sp, 0, (size_t)B_SZ * L_SZ * sizeof(float), 0);

    init_mats<<<(80 * 100 * 4 + 255) / 256, 256>>>(W1, W2, W3);

    cudaFuncSetAttribute(fused_kernel, cudaFuncAttributeMaxDynamicSharedMemorySize, SMEM_BYTES);
    dim3 grid((T_FR + TM - 1) / TM, B_SZ);
    fused_kernel<<<grid, NTHREADS, SMEM_BYTES>>>(noisy, clean, b1, p1, b2, p2, b3,
                                                 out_dct, cln_dct, out_sp);
}